// round 2
// baseline (speedup 1.0000x reference)
#include <cuda_runtime.h>
#include <cstdint>

// Problem constants (from reference)
#define PCR0      (-51.2f)
#define VX        (0.05f)
#define STRIDE_F  (4.0f)
#define FW        512
#define FH        512
#define NUM_CLASSES 10
#define NUM_MAX_OBJS 500
#define BATCH     16
#define OVERLAP   (0.1f)
#define MIN_RADIUS 2
#define RMAX      16
#define EPS_F32   (1.1920929e-07f)

// Output layout (float32, concatenated in reference-return order)
#define HEAT_ELEMS   ((size_t)BATCH * NUM_CLASSES * FH * FW)   // 41,943,040
#define BOXES_ELEMS  ((size_t)BATCH * NUM_MAX_OBJS * 8)        // 64,000
#define INDS_ELEMS   ((size_t)BATCH * NUM_MAX_OBJS)            // 8,000

// Pipeline: split heatmap memset + splat into chunks of batches, overlapped
#define NCHUNK    8
#define B_PER     (BATCH / NCHUNK)   // 2 batches per chunk

__device__ __forceinline__ float gaussian_radius(float h, float w, float ov) {
    float b1 = h + w;
    float c1 = w * h * (1.0f - ov) / (1.0f + ov);
    float sq1 = sqrtf(fmaxf(b1 * b1 - 4.0f * c1, 0.0f));
    float r1 = (b1 + sq1) * 0.5f;

    float b2 = 2.0f * (h + w);
    float c2 = (1.0f - ov) * w * h;
    float sq2 = sqrtf(fmaxf(b2 * b2 - 16.0f * c2, 0.0f));
    float r2 = (b2 + sq2) * 0.5f;

    float a3 = 4.0f * ov;
    float b3 = -2.0f * ov * (h + w);
    float c3 = (ov - 1.0f) * w * h;
    float sq3 = sqrtf(fmaxf(b3 * b3 - 4.0f * a3 * c3, 0.0f));
    float r3 = (b3 + sq3) / (2.0f * a3);

    return fminf(fminf(r1, r2), r3);
}

__global__ void __launch_bounds__(128) splat_kernel(
        const float* __restrict__ gt,
        float* __restrict__ heat,
        float* __restrict__ boxes,
        float* __restrict__ inds,
        float* __restrict__ mask,
        int b0)  // first batch handled by this chunk
{
    const int obj = b0 * NUM_MAX_OBJS + blockIdx.x;
    const int b   = obj / NUM_MAX_OBJS;

    const float* g = gt + (size_t)obj * 8;
    const float x  = g[0], y  = g[1], z  = g[2];
    const float dx = g[3], dy = g[4], dz = g[5];
    const float hd = g[6];
    const int   cls = (int)(g[7] - 1.0f);

    float coord_x = (x - PCR0) / VX / STRIDE_F;
    float coord_y = (y - PCR0) / VX / STRIDE_F;
    coord_x = fminf(fmaxf(coord_x, 0.0f), (float)FW - 0.5f);
    coord_y = fminf(fmaxf(coord_y, 0.0f), (float)FH - 0.5f);
    const int cxi = (int)coord_x;
    const int cyi = (int)coord_y;

    const float dxf = dx / VX / STRIDE_F;
    const float dyf = dy / VX / STRIDE_F;

    float radf = gaussian_radius(dxf, dyf, OVERLAP);
    int r = (int)radf;
    r = min(max(r, MIN_RADIUS), RMAX);

    const bool valid = (dxf > 0.0f) && (dyf > 0.0f) &&
                       (cxi >= 0) && (cxi <= FW) &&
                       (cyi >= 0) && (cyi <= FH);

    if (threadIdx.x == 0) {
        const float vf = valid ? 1.0f : 0.0f;
        float* bo = boxes + (size_t)obj * 8;
        bo[0] = (coord_x - (float)cxi) * vf;
        bo[1] = (coord_y - (float)cyi) * vf;
        bo[2] = z * vf;
        bo[3] = logf(fmaxf(dx, 1e-12f)) * vf;
        bo[4] = logf(fmaxf(dy, 1e-12f)) * vf;
        bo[5] = logf(fmaxf(dz, 1e-12f)) * vf;
        bo[6] = cosf(hd) * vf;
        bo[7] = sinf(hd) * vf;
        inds[obj] = valid ? (float)(cyi * FW + cxi) : 0.0f;
        mask[obj] = vf;
    }

    // 1D Gaussian factor table: ex[k] = exp(-k^2 / (2 sigma^2)), k = 0..r
    __shared__ float exs[RMAX + 1];
    const float sigma  = (2.0f * (float)r + 1.0f) / 6.0f;
    const float inv2s2 = 1.0f / (2.0f * sigma * sigma);
    if (threadIdx.x <= (unsigned)r) {
        const float k = (float)threadIdx.x;
        exs[threadIdx.x] = expf(-(k * k) * inv2s2);
    }
    __syncthreads();

    if (!valid) return;   // block-uniform

    const int c = min(max(cls, 0), NUM_CLASSES - 1);
    float* plane = heat + ((size_t)(b * NUM_CLASSES + c) * FH) * FW;

    const int side = 2 * r + 1;       // <= 33
    const int lane = threadIdx.x & 31;
    const int warp = threadIdx.x >> 5;

    // lane -> column offset(s); warp -> rows (strided by 4)
    const int   oj0 = lane - r;
    const bool  c0  = (lane < side);
    const float fj0 = c0 ? exs[abs(oj0)] : 0.0f;
    const int   oj1 = lane + 32 - r;                 // only when side == 33
    const bool  c1  = (lane + 32 < side);
    const float fj1 = c1 ? exs[abs(oj1)] : 0.0f;

    for (int row = warp; row < side; row += 4) {
        const int oi = row - r;
        const int yy = cyi + oi;
        if ((unsigned)yy >= FH) continue;
        const float fi = exs[abs(oi)];               // broadcast LDS
        unsigned int* prow = (unsigned int*)&plane[(size_t)yy * FW];

        if (c0) {
            const int xx = cxi + oj0;
            if ((unsigned)xx < FW) {
                const float gv = fi * fj0;
                if (gv >= EPS_F32)
                    atomicMax(prow + xx, __float_as_uint(gv));
            }
        }
        if (c1) {
            const int xx = cxi + oj1;
            if ((unsigned)xx < FW) {
                const float gv = fi * fj1;
                if (gv >= EPS_F32)
                    atomicMax(prow + xx, __float_as_uint(gv));
            }
        }
    }
}

extern "C" void kernel_launch(void* const* d_in, const int* in_sizes, int n_in,
                              void* d_out, int out_size) {
    const float* gt = (const float*)d_in[0];
    float* out = (float*)d_out;

    float* heat  = out;
    float* boxes = out + HEAT_ELEMS;
    float* inds  = out + HEAT_ELEMS + BOXES_ELEMS;
    float* mask  = out + HEAT_ELEMS + BOXES_ELEMS + INDS_ELEMS;

    // One-time resources (no device memory; streams/events only).
    static cudaStream_t s1 = nullptr;
    static cudaEvent_t evM[NCHUNK];
    static cudaEvent_t evJoin = nullptr;
    if (s1 == nullptr) {
        cudaStreamCreateWithFlags(&s1, cudaStreamNonBlocking);
        for (int i = 0; i < NCHUNK; i++)
            cudaEventCreateWithFlags(&evM[i], cudaEventDisableTiming);
        cudaEventCreateWithFlags(&evJoin, cudaEventDisableTiming);
    }

    const size_t chunk_elems = (size_t)B_PER * NUM_CLASSES * FH * FW;

    // Pipelined fork/join: memsets on the origin (capture) stream,
    // per-chunk splats on s1 gated by events. boxes/inds/mask are fully
    // written by splat_kernel (valid and invalid slots), so only the
    // heatmap region needs zeroing.
    for (int i = 0; i < NCHUNK; i++) {
        cudaMemsetAsync(heat + (size_t)i * chunk_elems, 0,
                        chunk_elems * sizeof(float), 0);
        cudaEventRecord(evM[i], 0);
        cudaStreamWaitEvent(s1, evM[i], 0);
        splat_kernel<<<B_PER * NUM_MAX_OBJS, 128, 0, s1>>>(
            gt, heat, boxes, inds, mask, i * B_PER);
    }
    cudaEventRecord(evJoin, s1);
    cudaStreamWaitEvent(0, evJoin, 0);
}